// round 14
// baseline (speedup 1.0000x reference)
#include <cuda_runtime.h>
#include <cuda_fp16.h>
#include <cstdint>

#define BB 32
#define CC 256
#define TT 1024
#define QKVW 384
#define MT (BB*TT)
#define CONVK 768

typedef uint32_t u32;

// ---------------- scratch (device globals; zero-initialized BSS) -------------
__device__ float g_bcat[QKVW];
__device__ float g_ssp[(size_t)MT*16];       // sumexp partials per i-tile
__device__ float g_rz[MT];
__device__ float g_rowsum[MT];
__device__ float g_wx[MT];
// plain fp16 operands
__device__ __align__(16) __half g_xth[(size_t)MT*CC];   // x^T [t][c]
__device__ __align__(16) __half g_wcbh[QKVW*CC];        // wcat^T [n][c]
__device__ __align__(16) __half g_qh[(size_t)MT*64];
__device__ __align__(16) __half g_kh[(size_t)MT*64];
__device__ __align__(16) __half g_vth[(size_t)BB*CC*TT]; // v^T [b][c][t], rz-scaled
__device__ __align__(16) __half g_e[(size_t)BB*TT*TT];   // e=exp(s) [b][j][i]; 0 outside band
__device__ __align__(16) __half g_h1h[(size_t)MT*CC];
__device__ __align__(16) __half g_h2h[(size_t)MT*CC];
__device__ __align__(16) __half g_w1bh[CC*CONVK];
__device__ __align__(16) __half g_w2bh[CC*CONVK];

// ---------------- helpers ----------------------------------------------------
__device__ __forceinline__ u32 smem_u32(const void* p) {
    u32 a;
    asm("{ .reg .u64 t; cvta.to.shared.u64 t, %1; cvt.u32.u64 %0, t; }"
        : "=r"(a) : "l"(p));
    return a;
}
__device__ __forceinline__ void cp16(u32 dst, const void* src, bool ok) {
    int sz = ok ? 16 : 0;
    asm volatile("cp.async.cg.shared.global [%0], [%1], 16, %2;"
                 :: "r"(dst), "l"(src), "r"(sz) : "memory");
}
#define CP_COMMIT() asm volatile("cp.async.commit_group;" ::: "memory")
#define CP_WAIT1()  asm volatile("cp.async.wait_group 1;" ::: "memory")
#define CP_WAIT0()  asm volatile("cp.async.wait_group 0;" ::: "memory")

__device__ __forceinline__ void mma16816(float c[4], const u32 a[4], const u32 b[2]) {
    asm volatile(
        "mma.sync.aligned.m16n8k16.row.col.f32.f16.f16.f32 "
        "{%0,%1,%2,%3}, {%4,%5,%6,%7}, {%8,%9}, {%0,%1,%2,%3};"
        : "+f"(c[0]), "+f"(c[1]), "+f"(c[2]), "+f"(c[3])
        : "r"(a[0]), "r"(a[1]), "r"(a[2]), "r"(a[3]), "r"(b[0]), "r"(b[1]));
}
__device__ __forceinline__ void ldsm4(u32& r0, u32& r1, u32& r2, u32& r3, u32 addr) {
    asm volatile("ldmatrix.sync.aligned.m8n8.x4.shared.b16 {%0,%1,%2,%3}, [%4];"
                 : "=r"(r0), "=r"(r1), "=r"(r2), "=r"(r3) : "r"(addr));
}
__device__ __forceinline__ void ldsm4t(u32& r0, u32& r1, u32& r2, u32& r3, u32 addr) {
    asm volatile("ldmatrix.sync.aligned.m8n8.x4.trans.shared.b16 {%0,%1,%2,%3}, [%4];"
                 : "=r"(r0), "=r"(r1), "=r"(r2), "=r"(r3) : "r"(addr));
}

// ---- stage geometry (swizzled, no padding): rows of 64B, 16B chunk XOR ------
#define SWZ(row, chunk) ((u32)((row)*64 + ((((chunk) ^ (((row) >> 1) & 3))) << 4)))
#define A_MATB 8192            // A: 128r x 64B  (or av: 32r x 256B)
#define B_MATB 4096            // B: 64r x 64B
#define STG (A_MATB + B_MATB)  // 12288
#define MMA_SMEM (3*STG)       // 36864

// one K=32 chunk via ldmatrix: warp tile 32(M) x 32(N), plain fp16
__device__ __forceinline__ void mma_chunk4(u32 base, u32 aA0, u32 aA1,
                                           u32 bB0, u32 bB1,
                                           float acc[2][4][4]) {
#pragma unroll
    for (int ks = 0; ks < 2; ks++) {
        u32 aoffk = ks ? aA1 : aA0;
        u32 boffk = ks ? bB1 : bB0;
        u32 ah[2][4];
#pragma unroll
        for (int mt = 0; mt < 2; mt++) {
            u32 ad = base + aoffk + mt*1024;
            ldsm4(ah[mt][0], ah[mt][1], ah[mt][2], ah[mt][3], ad);
        }
        u32 bh[4][2];
#pragma unroll
        for (int pr = 0; pr < 2; pr++) {
            u32 bd = base + A_MATB + boffk + pr*1024;
            u32 r0, r1, r2, r3;
            ldsm4(r0, r1, r2, r3, bd);
            bh[2*pr][0] = r0; bh[2*pr][1] = r1;
            bh[2*pr+1][0] = r2; bh[2*pr+1][1] = r3;
        }
#pragma unroll
        for (int mt = 0; mt < 2; mt++)
#pragma unroll
            for (int nt = 0; nt < 4; nt++)
                mma16816(acc[mt][nt], ah[mt], bh[nt]);
    }
}

// av chunk: A from [j][i] storage (32 rows x 256B, chunk XOR j&7) via ldmatrix.trans
__device__ __forceinline__ void mma_chunk_av(u32 base, int warp_m,
                                             u32 jr_l, u32 ch_add,
                                             u32 bB0, u32 bB1,
                                             float acc[2][4][4]) {
#pragma unroll
    for (int ks = 0; ks < 2; ks++) {
        u32 ah[2][4];
#pragma unroll
        for (int mt = 0; mt < 2; mt++) {
            u32 ad = base + (ks*16 + jr_l)*256
                   + ((((u32)(warp_m*4 + mt*2) + ch_add) ^ (jr_l & 7)) << 4);
            ldsm4t(ah[mt][0], ah[mt][1], ah[mt][2], ah[mt][3], ad);
        }
        u32 boffk = ks ? bB1 : bB0;
        u32 bh[4][2];
#pragma unroll
        for (int pr = 0; pr < 2; pr++) {
            u32 bd = base + A_MATB + boffk + pr*1024;
            u32 r0, r1, r2, r3;
            ldsm4(r0, r1, r2, r3, bd);
            bh[2*pr][0] = r0; bh[2*pr][1] = r1;
            bh[2*pr+1][0] = r2; bh[2*pr+1][1] = r3;
        }
#pragma unroll
        for (int mt = 0; mt < 2; mt++)
#pragma unroll
            for (int nt = 0; nt < 4; nt++)
                mma16816(acc[mt][nt], ah[mt], bh[nt]);
    }
}

// per-warp ldmatrix swizzled base offsets (ks=0 / ks=1 pre-XORed)
#define LDSM_OFFS()                                                           \
    u32 mx = (lane >> 1) & 3;                                                 \
    u32 rA = (u32)(warp_m*32 + (lane & 15));                                  \
    u32 cAb = (u32)(lane >> 4);                                               \
    u32 aA0 = rA*64 + ((cAb ^ mx) << 4);                                      \
    u32 aA1 = rA*64 + (((cAb ^ 2) ^ mx) << 4);                                \
    u32 rB = (u32)(warp_n*32 + ((lane >> 4) << 3) + (lane & 7));              \
    u32 cBb = (u32)((lane >> 3) & 1);                                         \
    u32 bB0 = rB*64 + ((cBb ^ mx) << 4);                                      \
    u32 bB1 = rB*64 + (((cBb ^ 2) ^ mx) << 4);

// 3-stage mainloop, one sync per chunk, 2 loads in flight.
#define MMA_MAINLOOP(NCH, CHUNK_CALL)                                         \
    { ISSUE(0, sbase); } CP_COMMIT();                                         \
    { ISSUE(1, sbase + STG); } CP_COMMIT();                                   \
    for (int cc = 0; cc < (NCH); cc++) {                                      \
        u32 sb = sbase + (u32)(cc % 3)*STG;                                   \
        if (cc + 1 < (NCH)) { CP_WAIT1(); } else { CP_WAIT0(); }              \
        __syncthreads();                                                      \
        if (cc + 2 < (NCH)) {                                                 \
            ISSUE(cc + 2, sbase + (u32)((cc + 2) % 3)*STG);                   \
            CP_COMMIT();                                                      \
        }                                                                     \
        CHUNK_CALL;                                                           \
    }

// ---------------- prep: transpose x to fp16 [t][c] ---------------------------
__global__ void k_prep_xt(const float* __restrict__ x) {
    __shared__ float sm[32][33];
    int t0 = blockIdx.x * 32, c0 = blockIdx.y * 32, b = blockIdx.z;
    int lane = threadIdx.x & 31, grp = threadIdx.x >> 5;
#pragma unroll
    for (int r = 0; r < 4; r++) {
        int c = grp + r*8;
        sm[c][lane] = x[((size_t)b*CC + c0 + c)*TT + t0 + lane];
    }
    __syncthreads();
#pragma unroll
    for (int r = 0; r < 4; r++) {
        int t = grp + r*8;
        size_t idx = (size_t)(b*TT + t0 + t)*CC + c0 + lane;
        g_xth[idx] = __float2half(sm[lane][t]);
    }
}

// ---------------- prep: wcat^T (fp16) + bcat ---------------------------------
__global__ void k_prep_wcat(const float* __restrict__ wq, const float* __restrict__ bq,
                            const float* __restrict__ wk, const float* __restrict__ bk,
                            const float* __restrict__ wv, const float* __restrict__ bv) {
    int n = blockIdx.x;
    int c = threadIdx.x;
    float w;
    if (n < 64)       w = wq[c*64 + n];
    else if (n < 128) w = wk[c*64 + (n-64)];
    else              w = wv[c*256 + (n-128)];
    g_wcbh[n*CC + c] = __float2half(w);
    if (c == 0)
        g_bcat[n] = (n < 64) ? bq[n] : (n < 128) ? bk[n-64] : bv[n-128];
}

// ---------------- prep: weight-norm conv weights (fp16) ----------------------
__global__ void k_prep_convw(const float* __restrict__ v1, const float* __restrict__ g1,
                             const float* __restrict__ v2, const float* __restrict__ g2) {
    int layer = blockIdx.x >> 8;
    int o = blockIdx.x & 255;
    const float* v = layer ? v2 : v1;
    const float* g = layer ? g2 : g1;
    __half* wh = layer ? g_w2bh : g_w1bh;
    int tid = threadIdx.x;
    float vv[3];
    float part = 0.f;
#pragma unroll
    for (int k = 0; k < 3; k++) {
        vv[k] = v[((size_t)o*CC + tid)*3 + k];
        part += vv[k]*vv[k];
    }
    __shared__ float sm[256];
    sm[tid] = part; __syncthreads();
    for (int s = 128; s > 0; s >>= 1) {
        if (tid < s) sm[tid] += sm[tid+s];
        __syncthreads();
    }
    float scale = g[o] * rsqrtf(sm[0]);
#pragma unroll
    for (int k = 0; k < 3; k++)
        wh[(size_t)o*CONVK + k*CC + tid] = __float2half(scale * vv[k]);
}

// ---------------- qkv GEMM -----------------------------------------------------
__global__ void __launch_bounds__(256, 3) k_qkv_mma() {
    extern __shared__ __align__(128) char smem[];
    int m0 = blockIdx.x * 128;
    int n0 = blockIdx.y * 64;
    int tid = threadIdx.x;
    int wid = tid >> 5, lane = tid & 31;
    int warp_m = wid & 3, warp_n = wid >> 2;
    int g = lane >> 2, tg = lane & 3;
    u32 sbase = smem_u32(smem);
    int arow = tid >> 1, ahalf = tid & 1;
    int brow = tid >> 2, bq4 = tid & 3;
    LDSM_OFFS()

    float acc[2][4][4];
#pragma unroll
    for (int a = 0; a < 2; a++)
#pragma unroll
        for (int c = 0; c < 4; c++)
#pragma unroll
            for (int d = 0; d < 4; d++) acc[a][c][d] = 0.f;

#define ISSUE(cc, st) do {                                                    \
        size_t ga = (size_t)(m0 + arow)*CC + (cc)*32 + ahalf*16;              \
        cp16((st) + SWZ(arow, ahalf*2),     g_xth + ga,     true);            \
        cp16((st) + SWZ(arow, ahalf*2 + 1), g_xth + ga + 8, true);            \
        size_t gb = (size_t)(n0 + brow)*CC + (cc)*32 + bq4*8;                 \
        cp16((st) + A_MATB + SWZ(brow, bq4), g_wcbh + gb, true);              \
    } while (0)

    MMA_MAINLOOP(8, mma_chunk4(sb, aA0, aA1, bB0, bB1, acc))
#undef ISSUE

    int b = m0 >> 10, t0 = m0 & 1023;
#pragma unroll
    for (int mt = 0; mt < 2; mt++) {
        int mr = warp_m*32 + mt*16 + g;
#pragma unroll
        for (int nt = 0; nt < 4; nt++) {
            int n = n0 + warp_n*32 + nt*8 + tg*2;
            float* c = acc[mt][nt];
            float v00 = c[0] + g_bcat[n],   v01 = c[1] + g_bcat[n+1];
            float v10 = c[2] + g_bcat[n],   v11 = c[3] + g_bcat[n+1];
            if (n < 128) {
                __half* ph = (n < 64) ? g_qh : g_kh;
                int nn = n & 63;
                size_t i_lo = (size_t)(m0 + mr)*64 + nn;
                size_t i_hi = (size_t)(m0 + mr + 8)*64 + nn;
                *(__half2*)&ph[i_lo] =
                    __halves2half2(__float2half(v00), __float2half(v01));
                *(__half2*)&ph[i_hi] =
                    __halves2half2(__float2half(v10), __float2half(v11));
            } else {
                int cch = n - 128;
                int t_lo = t0 + mr, t_hi = t_lo + 8;
                size_t b00 = ((size_t)b*CC + cch)*TT;
                g_vth[b00 + t_lo]      = __float2half(v00);
                g_vth[b00 + t_hi]      = __float2half(v10);
                g_vth[b00 + TT + t_lo] = __float2half(v01);
                g_vth[b00 + TT + t_hi] = __float2half(v11);
            }
        }
    }
}

// --- scores GEMM: e[b][j][i] = exp(k.q/8) masked (fp16) + sum partials -------
__global__ void __launch_bounds__(256, 3) k_scores_mma() {
    int i0 = blockIdx.x * 64, j0 = blockIdx.y * 128, b = blockIdx.z;
    if (j0 > i0 + 63) return;
    extern __shared__ __align__(128) char smem[];
    __shared__ float s_sum[128][2];
    int tid = threadIdx.x;
    int wid = tid >> 5, lane = tid & 31;
    int warp_m = wid & 3, warp_n = wid >> 2;
    int g = lane >> 2, tg = lane & 3;
    u32 sbase = smem_u32(smem);
    int arow = tid >> 1, ahalf = tid & 1;
    int brow = tid >> 2, bq4 = tid & 3;
    LDSM_OFFS()

    float acc[2][4][4];
#pragma unroll
    for (int a = 0; a < 2; a++)
#pragma unroll
        for (int c = 0; c < 4; c++)
#pragma unroll
            for (int d = 0; d < 4; d++) acc[a][c][d] = 0.f;

    const __half* Ahp = g_kh + (size_t)(b*TT + j0)*64;
    const __half* Bhp = g_qh + (size_t)(b*TT + i0)*64;

#define ISSUE(cc, st) do {                                                    \
        size_t ga = (size_t)arow*64 + (cc)*32 + ahalf*16;                     \
        cp16((st) + SWZ(arow, ahalf*2),     Ahp + ga,     true);              \
        cp16((st) + SWZ(arow, ahalf*2 + 1), Ahp + ga + 8, true);              \
        size_t gb = (size_t)brow*64 + (cc)*32 + bq4*8;                        \
        cp16((st) + A_MATB + SWZ(brow, bq4), Bhp + gb, true);                 \
    } while (0)

    MMA_MAINLOOP(2, mma_chunk4(sb, aA0, aA1, bB0, bB1, acc))
#undef ISSUE

    size_t base = (size_t)b*TT*TT;
    float psum[2];
#pragma unroll
    for (int mt = 0; mt < 2; mt++) {
        int j_lo = j0 + warp_m*32 + mt*16 + g;
        int j_hi = j_lo + 8;
        psum[0] = 0.f; psum[1] = 0.f;
#pragma unroll
        for (int nt = 0; nt < 4; nt++) {
            int i = i0 + warp_n*32 + nt*8 + tg*2;
            float* c = acc[mt][nt];
            float e0 = (i   >= j_lo) ? __expf(c[0]*0.125f) : 0.f;
            float e1 = (i+1 >= j_lo) ? __expf(c[1]*0.125f) : 0.f;
            float e2 = (i   >= j_hi) ? __expf(c[2]*0.125f) : 0.f;
            float e3 = (i+1 >= j_hi) ? __expf(c[3]*0.125f) : 0.f;
            *(__half2*)&g_e[base + (size_t)j_lo*TT + i] =
                __halves2half2(__float2half(e0), __float2half(e1));
            *(__half2*)&g_e[base + (size_t)j_hi*TT + i] =
                __halves2half2(__float2half(e2), __float2half(e3));
            psum[0] += e0 + e1;
            psum[1] += e2 + e3;
        }
        float p0 = psum[0], p1 = psum[1];
        p0 += __shfl_xor_sync(0xffffffffu, p0, 1);
        p0 += __shfl_xor_sync(0xffffffffu, p0, 2);
        p1 += __shfl_xor_sync(0xffffffffu, p1, 1);
        p1 += __shfl_xor_sync(0xffffffffu, p1, 2);
        if (tg == 0) {
            int rl = warp_m*32 + mt*16 + g;
            s_sum[rl][warp_n]     = p0;
            s_sum[rl + 8][warp_n] = p1;
        }
    }
    __syncthreads();
    if (tid < 128) {
        float s = s_sum[tid][0] + s_sum[tid][1];
        g_ssp[(size_t)(b*TT + j0 + tid)*16 + (i0 >> 6)] = s;
    }
}

// ---------------- rz[row] = 1 / sumexp ---------------------------------------
__global__ void k_rz() {
    int row = blockIdx.x * 256 + threadIdx.x;
    int j = row & 1023;
    const float* p = &g_ssp[(size_t)row*16];
    float s = 0.f;
    for (int k = (j >> 6); k < 16; k++) s += p[k];
    g_rz[row] = 1.f / s;
}

// ---------------- v' = rz * v (in place, fp16) -------------------------------
__global__ void k_vscale() {
    size_t idx = ((size_t)blockIdx.x*256 + threadIdx.x)*2;
    int b = (int)(idx >> 18);
    int t = (int)(idx & 1023);
    __half2 v = *(const __half2*)&g_vth[idx];
    float2 f = __half22float2(v);
    float2 rz2 = *(const float2*)&g_rz[(b << 10) + t];
    f.x *= rz2.x; f.y *= rz2.y;
    *(__half2*)&g_vth[idx] = __floats2half2_rn(f.x, f.y);
}

// ---------------- rowsum[b,i] = sum_j e[j][i]*rz[j] --------------------------
__global__ void k_rowsum() {
    int i0 = blockIdx.x * 64, b = blockIdx.y;
    int tid = threadIdx.x;
    int il = tid & 63, jr = tid >> 6;
    const __half* pe = g_e + (size_t)b*TT*TT;
    const float* rz = g_rz + b*TT;
    float s = 0.f;
    int jmax = i0 + 64;
    for (int j = jr; j < jmax; j += 4)
        s += __half2float(pe[(size_t)j*TT + i0 + il]) * rz[j];
    __shared__ float sp[4][64];
    sp[jr][il] = s; __syncthreads();
    if (tid < 64)
        g_rowsum[b*TT + i0 + tid] = sp[0][tid] + sp[1][tid] + sp[2][tid] + sp[3][tid];
}

// ---------------- weight_x = softmax_t(rowsum) -------------------------------
__global__ void k_wx() {
    int b = blockIdx.x, tid = threadIdx.x;
    __shared__ float sm[256];
    float v[4], e[4];
    float mx = -1e30f;
#pragma unroll
    for (int r = 0; r < 4; r++) {
        v[r] = g_rowsum[b*TT + tid + r*256];
        mx = fmaxf(mx, v[r]);
    }
    sm[tid] = mx; __syncthreads();
    for (int s = 128; s > 0; s >>= 1) {
        if (tid < s) sm[tid] = fmaxf(sm[tid], sm[tid+s]);
        __syncthreads();
    }
    mx = sm[0]; __syncthreads();
    float sum = 0.f;
#pragma unroll
    for (int r = 0; r < 4; r++) { e[r] = __expf(v[r] - mx); sum += e[r]; }
    sm[tid] = sum; __syncthreads();
    for (int s = 128; s > 0; s >>= 1) {
        if (tid < s) sm[tid] += sm[tid+s];
        __syncthreads();
    }
    float rz = 1.f / sm[0];
#pragma unroll
    for (int r = 0; r < 4; r++) g_wx[b*TT + tid + r*256] = e[r] * rz;
}

// ---------------- av GEMM: h1[i][c] = e @ v', A via ldmatrix.trans -----------
__global__ void __launch_bounds__(256, 3) k_av_mma() {
    extern __shared__ __align__(128) char smem[];
    int m0 = blockIdx.x * 128;
    int n0 = blockIdx.y * 64;
    int b = m0 >> 10, t0 = m0 & 1023;
    int tid = threadIdx.x;
    int wid = tid >> 5, lane = tid & 31;
    int warp_m = wid & 3, warp_n = wid >> 2;
    int g = lane >> 2, tg = lane & 3;
    u32 sbase = smem_u32(smem);
    int brow = tid >> 2, bq4 = tid & 3;
    // B ldmatrix offsets (same as shared kernels)
    u32 mx = (lane >> 1) & 3;
    u32 rB = (u32)(warp_n*32 + ((lane >> 4) << 3) + (lane & 7));
    u32 cBb = (u32)((lane >> 3) & 1);
    u32 bB0 = rB*64 + ((cBb ^ mx) << 4);
    u32 bB1 = rB*64 + (((cBb ^ 2) ^ mx) << 4);
    // A trans-load lane geometry
    u32 jr_l = (u32)((lane & 7) + ((lane >> 4) << 3));   // 0..15
    u32 ch_add = (u32)((lane >> 3) & 1);
    // A cp.async loader mapping: 32 rows x 16 chunks
    int jrow = tid >> 3, jch = tid & 7;

    float acc[2][4][4];
#pragma unroll
    for (int a = 0; a < 2; a++)
#pragma unroll
        for (int c = 0; c < 4; c++)
#pragma unroll
            for (int d = 0; d < 4; d++) acc[a][c][d] = 0.f;

    const __half* Ep  = g_e + (size_t)b*TT*TT;
    const __half* Bhp = g_vth + ((size_t)b*CC + n0)*TT;
    int nch = (t0 + 128) >> 5;

#define ISSUE(cc, st) do {                                                    \
        size_t ga = (size_t)((cc)*32 + jrow)*TT + t0 + jch*8;                 \
        u32 sw0 = (st) + jrow*256 + (((jch)     ^ (jrow & 7)) << 4);          \
        u32 sw1 = (st) + jrow*256 + (((jch + 8) ^ (jrow & 7)) << 4);          \
        cp16(sw0, Ep + ga,      true);                                        \
        cp16(sw1, Ep + ga + 64, true);                                        \
        size_t gb = (size_t)brow*TT + (cc)*32 + bq4*8;                        \
        cp16((st) + A_MATB + SWZ(brow, bq4), Bhp + gb, true);                 \
    } while (0)

    MMA_MAINLOOP(nch, mma_chunk_av(sb, warp_m, jr_l, ch_add, bB0, bB1, acc))
#undef ISSUE

#pragma unroll
    for (int mt = 0; mt < 2; mt++) {
        int m_lo = m0 + warp_m*32 + mt*16 + g;
#pragma unroll
        for (int nt = 0; nt < 4; nt++) {
            int n = n0 + warp_n*32 + nt*8 + tg*2;
            float* c = acc[mt][nt];
            size_t i_lo = (size_t)m_lo*CC + n;
            size_t i_hi = (size_t)(m_lo+8)*CC + n;
            *(__half2*)&g_h1h[i_lo] =
                __halves2half2(__float2half(c[0]), __float2half(c[1]));
            *(__half2*)&g_h1h[i_hi] =
                __halves2half2(__float2half(c[2]), __float2half(c[3]));
        }
    }
}

// ---------------- conv GEMM --------------------------------------------------
__global__ void __launch_bounds__(256, 3) k_conv_mma(int mode,
                                                     const float* __restrict__ bias,
                                                     const float* __restrict__ x,
                                                     float* __restrict__ outp) {
    extern __shared__ __align__(128) char smem[];
    const __half* Ahp = mode ? g_h2h  : g_h1h;
    const __half* Bhp = mode ? g_w2bh : g_w1bh;

    int m0 = blockIdx.x * 128;
    int n0 = blockIdx.y * 64;
    int b = m0 >> 10, t0 = m0 & 1023;
    int tid = threadIdx.x;
    int wid = tid >> 5, lane = tid & 31;
    int warp_m = wid & 3, warp_n = wid >> 2;
    int g = lane >> 2, tg = lane & 3;
    u32 sbase = smem_u32(smem);
    int arow = tid >> 1, ahalf = tid & 1;
    int brow = tid >> 2, bq4 = tid & 3;
    LDSM_OFFS()

    float acc[2][4][4];
#pragma unroll
    for (int a = 0; a < 2; a++)
#pragma unroll
        for (int c = 0; c < 4; c++)
#pragma unroll
            for (int d = 0; d < 4; d++) acc[a][c][d] = 0.f;

#define ISSUE(cc, st) do {                                                    \
        int koff = (cc) >> 3, i0c = ((cc) & 7) * 32;                          \
        int t = t0 + arow + koff - 2;                                         \
        bool ok = (t >= 0);                                                   \
        size_t ga = (size_t)(b*TT + t)*CC + i0c + ahalf*16;                   \
        cp16((st) + SWZ(arow, ahalf*2),     Ahp + ga,     ok);                \
        cp16((st) + SWZ(arow, ahalf*2 + 1), Ahp + ga + 8, ok);                \
        size_t gb = (size_t)(n0 + brow)*CONVK + (cc)*32 + bq4*8;              \
        cp16((st) + A_MATB + SWZ(brow, bq4), Bhp + gb, true);                 \
    } while (0)

    MMA_MAINLOOP(24, mma_chunk4(sb, aA0, aA1, bB0, bB1, acc))
#undef ISSUE

#pragma unroll
    for (int mt = 0; mt < 2; mt++) {
        int t_lo = t0 + warp_m*32 + mt*16 + g;
        int t_hi = t_lo + 8;
        if (mode == 0) {
#pragma unroll
            for (int nt = 0; nt < 4; nt++) {
                int n = n0 + warp_n*32 + nt*8 + tg*2;
                float b0 = bias[n], b1 = bias[n+1];
                float* c = acc[mt][nt];
                float v0 = fmaxf(c[0] + b0, 0.f);
                float v1 = fmaxf(c[1] + b1, 0.f);
                float v2 = fmaxf(c[2] + b0, 0.f);
                float v3 = fmaxf(c[3] + b1, 0.f);
                size_t i_lo = (size_t)(b*TT + t_lo)*CC + n;
                size_t i_hi = (size_t)(b*TT + t_hi)*CC + n;
                *(__half2*)&g_h2h[i_lo] =
                    __halves2half2(__float2half(v0), __float2half(v1));
                *(__half2*)&g_h2h[i_hi] =
                    __halves2half2(__float2half(v2), __float2half(v3));
            }
        } else {
            float w_lo = 1.f + g_wx[b*TT + t_lo];
            float w_hi = 1.f + g_wx[b*TT + t_hi];
#pragma unroll
            for (int nt = 0; nt < 4; nt++) {
                int n = n0 + warp_n*32 + nt*8 + tg*2;
                float b0 = bias[n], b1 = bias[n+1];
                float* c = acc[mt][nt];
                size_t o00 = ((size_t)b*CC + n)*TT + t_lo;
                size_t o10 = o00 + TT;
                size_t o01 = o00 + 8;
                size_t o11 = o10 + 8;
                outp[o00] = fmaxf(fmaxf(c[0] + b0, 0.f) + x[o00]*w_lo, 0.f);
                outp[o10] = fmaxf(fmaxf(c[1] + b1, 0.f) + x[o10]*w_lo, 0.f);
                outp[o01] = fmaxf(fmaxf(c[2] + b0, 0.f) + x[o01]*w_hi, 0.f);
                outp[o11] = fmaxf(fmaxf(c[3] + b1, 0.f) + x[o11]*w_hi, 0.f);
            }
        }
    }
}

// ---------------- launch ------------------------------------------------------
extern "C" void kernel_launch(void* const* d_in, const int* in_sizes, int n_in,
                              void* d_out, int out_size) {
    const float* x  = (const float*)d_in[0];
    const float* wq = (const float*)d_in[1];
    const float* bq = (const float*)d_in[2];
    const float* wk = (const float*)d_in[3];
    const float* bk = (const float*)d_in[4];
    const float* wv = (const float*)d_in[5];
    const float* bv = (const float*)d_in[6];
    const float* v1 = (const float*)d_in[7];
    const float* g1 = (const float*)d_in[8];
    const float* b1 = (const float*)d_in[9];
    const float* v2 = (const float*)d_in[10];
    const float* g2 = (const float*)d_in[11];
    const float* b2 = (const float*)d_in[12];
    float* out = (float*)d_out;

    static int smset = 0;
    if (!smset) {
        cudaFuncSetAttribute(k_qkv_mma,    cudaFuncAttributeMaxDynamicSharedMemorySize, MMA_SMEM);
        cudaFuncSetAttribute(k_scores_mma, cudaFuncAttributeMaxDynamicSharedMemorySize, MMA_SMEM);
        cudaFuncSetAttribute(k_av_mma,     cudaFuncAttributeMaxDynamicSharedMemorySize, MMA_SMEM);
        cudaFuncSetAttribute(k_conv_mma,   cudaFuncAttributeMaxDynamicSharedMemorySize, MMA_SMEM);
        smset = 1;
    }

    k_prep_xt<<<dim3(TT/32, CC/32, BB), 256>>>(x);
    k_prep_wcat<<<QKVW, 256>>>(wq, bq, wk, bk, wv, bv);
    k_prep_convw<<<512, 256>>>(v1, g1, v2, g2);
    k_qkv_mma<<<dim3(MT/128, QKVW/64), 256, MMA_SMEM>>>();
    k_scores_mma<<<dim3(16, 8, BB), 256, MMA_SMEM>>>();
    k_rz<<<MT/256, 256>>>();
    k_vscale<<<(BB*CC*TT)/512, 256>>>();
    k_rowsum<<<dim3(16, BB), 256>>>();
    k_wx<<<BB, 256>>>();
    k_av_mma<<<dim3(MT/128, CC/64), 256, MMA_SMEM>>>();
    k_conv_mma<<<dim3(MT/128, CC/64), 256, MMA_SMEM>>>(0, b1, x, out);
    k_conv_mma<<<dim3(MT/128, CC/64), 256, MMA_SMEM>>>(1, b2, x, out);
}

// round 15
// speedup vs baseline: 1.1174x; 1.1174x over previous
#include <cuda_runtime.h>
#include <cuda_fp16.h>
#include <cstdint>

#define BB 32
#define CC 256
#define TT 1024
#define QKVW 384
#define MT (BB*TT)
#define CONVK 768

typedef uint32_t u32;

// ---------------- scratch (device globals; zero-initialized BSS) -------------
__device__ float g_bcat[QKVW];
__device__ float g_ssp[(size_t)MT*16];       // sumexp partials per i-tile
__device__ float g_rz[MT];
__device__ float g_rsp[(size_t)MT*16];       // rowsum partials per j-tile
__device__ float g_wx[MT];
// plain fp16 operands
__device__ __align__(16) __half g_xth[(size_t)MT*CC];   // x^T [t][c]
__device__ __align__(16) __half g_wcbh[QKVW*CC];        // wcat^T [n][c]
__device__ __align__(16) __half g_qh[(size_t)MT*64];
__device__ __align__(16) __half g_kh[(size_t)MT*64];
__device__ __align__(16) __half g_vth[(size_t)BB*CC*TT]; // v^T [b][c][t]
__device__ __align__(16) __half g_e[(size_t)BB*TT*TT];   // e=exp(s) [b][j][i]
__device__ __align__(16) __half g_ath[(size_t)BB*TT*TT]; // attn [b][i][j]
__device__ __align__(16) __half g_h1h[(size_t)MT*CC];
__device__ __align__(16) __half g_h2h[(size_t)MT*CC];
__device__ __align__(16) __half g_w1bh[CC*CONVK];
__device__ __align__(16) __half g_w2bh[CC*CONVK];

// ---------------- helpers ----------------------------------------------------
__device__ __forceinline__ u32 smem_u32(const void* p) {
    u32 a;
    asm("{ .reg .u64 t; cvta.to.shared.u64 t, %1; cvt.u32.u64 %0, t; }"
        : "=r"(a) : "l"(p));
    return a;
}
__device__ __forceinline__ void cp16(u32 dst, const void* src, bool ok) {
    int sz = ok ? 16 : 0;
    asm volatile("cp.async.cg.shared.global [%0], [%1], 16, %2;"
                 :: "r"(dst), "l"(src), "r"(sz) : "memory");
}
#define CP_COMMIT() asm volatile("cp.async.commit_group;" ::: "memory")
#define CP_WAIT1()  asm volatile("cp.async.wait_group 1;" ::: "memory")
#define CP_WAIT0()  asm volatile("cp.async.wait_group 0;" ::: "memory")

__device__ __forceinline__ void mma16816(float c[4], const u32 a[4], const u32 b[2]) {
    asm volatile(
        "mma.sync.aligned.m16n8k16.row.col.f32.f16.f16.f32 "
        "{%0,%1,%2,%3}, {%4,%5,%6,%7}, {%8,%9}, {%0,%1,%2,%3};"
        : "+f"(c[0]), "+f"(c[1]), "+f"(c[2]), "+f"(c[3])
        : "r"(a[0]), "r"(a[1]), "r"(a[2]), "r"(a[3]), "r"(b[0]), "r"(b[1]));
}
__device__ __forceinline__ void ldsm4(u32& r0, u32& r1, u32& r2, u32& r3, u32 addr) {
    asm volatile("ldmatrix.sync.aligned.m8n8.x4.shared.b16 {%0,%1,%2,%3}, [%4];"
                 : "=r"(r0), "=r"(r1), "=r"(r2), "=r"(r3) : "r"(addr));
}

// ---- stage geometry (swizzled, no padding): rows of 64B, 16B chunk XOR ------
#define SWZ(row, chunk) ((u32)((row)*64 + ((((chunk) ^ (((row) >> 1) & 3))) << 4)))
#define A_MATB 8192            // 128 rows * 64 B
#define B_MATB 4096            // 64 rows * 64 B
#define STG (A_MATB + B_MATB)  // 12288 (A, B)
#define MMA_SMEM (3*STG)       // 36864 -> 3 CTAs/SM

// one K=32 chunk via ldmatrix: warp tile 32(M) x 32(N), plain fp16
__device__ __forceinline__ void mma_chunk4(u32 base, u32 aA0, u32 aA1,
                                           u32 bB0, u32 bB1,
                                           float acc[2][4][4]) {
#pragma unroll
    for (int ks = 0; ks < 2; ks++) {
        u32 aoffk = ks ? aA1 : aA0;
        u32 boffk = ks ? bB1 : bB0;
        u32 ah[2][4];
#pragma unroll
        for (int mt = 0; mt < 2; mt++) {
            u32 ad = base + aoffk + mt*1024;
            ldsm4(ah[mt][0], ah[mt][1], ah[mt][2], ah[mt][3], ad);
        }
        u32 bh[4][2];
#pragma unroll
        for (int pr = 0; pr < 2; pr++) {
            u32 bd = base + A_MATB + boffk + pr*1024;
            u32 r0, r1, r2, r3;
            ldsm4(r0, r1, r2, r3, bd);
            bh[2*pr][0] = r0; bh[2*pr][1] = r1;
            bh[2*pr+1][0] = r2; bh[2*pr+1][1] = r3;
        }
#pragma unroll
        for (int mt = 0; mt < 2; mt++)
#pragma unroll
            for (int nt = 0; nt < 4; nt++)
                mma16816(acc[mt][nt], ah[mt], bh[nt]);
    }
}

// per-warp ldmatrix swizzled base offsets (ks=0 / ks=1 pre-XORed)
#define LDSM_OFFS()                                                           \
    u32 mx = (lane >> 1) & 3;                                                 \
    u32 rA = (u32)(warp_m*32 + (lane & 15));                                  \
    u32 cAb = (u32)(lane >> 4);                                               \
    u32 aA0 = rA*64 + ((cAb ^ mx) << 4);                                      \
    u32 aA1 = rA*64 + (((cAb ^ 2) ^ mx) << 4);                                \
    u32 rB = (u32)(warp_n*32 + ((lane >> 4) << 3) + (lane & 7));              \
    u32 cBb = (u32)((lane >> 3) & 1);                                         \
    u32 bB0 = rB*64 + ((cBb ^ mx) << 4);                                      \
    u32 bB1 = rB*64 + (((cBb ^ 2) ^ mx) << 4);

// 3-stage mainloop, one sync per chunk, 2 loads in flight.
#define MMA_MAINLOOP(NCH)                                                     \
    { ISSUE(0, sbase); } CP_COMMIT();                                         \
    { ISSUE(1, sbase + STG); } CP_COMMIT();                                   \
    for (int cc = 0; cc < (NCH); cc++) {                                      \
        u32 sb = sbase + (u32)(cc % 3)*STG;                                   \
        if (cc + 1 < (NCH)) { CP_WAIT1(); } else { CP_WAIT0(); }              \
        __syncthreads();                                                      \
        if (cc + 2 < (NCH)) {                                                 \
            ISSUE(cc + 2, sbase + (u32)((cc + 2) % 3)*STG);                   \
            CP_COMMIT();                                                      \
        }                                                                     \
        mma_chunk4(sb, aA0, aA1, bB0, bB1, acc);                              \
    }

// ---------------- prep: transpose x to fp16 [t][c] ---------------------------
__global__ void k_prep_xt(const float* __restrict__ x) {
    __shared__ float sm[32][33];
    int t0 = blockIdx.x * 32, c0 = blockIdx.y * 32, b = blockIdx.z;
    int lane = threadIdx.x & 31, grp = threadIdx.x >> 5;
#pragma unroll
    for (int r = 0; r < 4; r++) {
        int c = grp + r*8;
        sm[c][lane] = x[((size_t)b*CC + c0 + c)*TT + t0 + lane];
    }
    __syncthreads();
#pragma unroll
    for (int r = 0; r < 4; r++) {
        int t = grp + r*8;
        size_t idx = (size_t)(b*TT + t0 + t)*CC + c0 + lane;
        g_xth[idx] = __float2half(sm[lane][t]);
    }
}

// ---------------- prep: wcat^T (fp16) + bcat ---------------------------------
__global__ void k_prep_wcat(const float* __restrict__ wq, const float* __restrict__ bq,
                            const float* __restrict__ wk, const float* __restrict__ bk,
                            const float* __restrict__ wv, const float* __restrict__ bv) {
    int n = blockIdx.x;
    int c = threadIdx.x;
    float w;
    if (n < 64)       w = wq[c*64 + n];
    else if (n < 128) w = wk[c*64 + (n-64)];
    else              w = wv[c*256 + (n-128)];
    g_wcbh[n*CC + c] = __float2half(w);
    if (c == 0)
        g_bcat[n] = (n < 64) ? bq[n] : (n < 128) ? bk[n-64] : bv[n-128];
}

// ---------------- prep: weight-norm conv weights (fp16) ----------------------
__global__ void k_prep_convw(const float* __restrict__ v1, const float* __restrict__ g1,
                             const float* __restrict__ v2, const float* __restrict__ g2) {
    int layer = blockIdx.x >> 8;
    int o = blockIdx.x & 255;
    const float* v = layer ? v2 : v1;
    const float* g = layer ? g2 : g1;
    __half* wh = layer ? g_w2bh : g_w1bh;
    int tid = threadIdx.x;
    float vv[3];
    float part = 0.f;
#pragma unroll
    for (int k = 0; k < 3; k++) {
        vv[k] = v[((size_t)o*CC + tid)*3 + k];
        part += vv[k]*vv[k];
    }
    __shared__ float sm[256];
    sm[tid] = part; __syncthreads();
    for (int s = 128; s > 0; s >>= 1) {
        if (tid < s) sm[tid] += sm[tid+s];
        __syncthreads();
    }
    float scale = g[o] * rsqrtf(sm[0]);
#pragma unroll
    for (int k = 0; k < 3; k++)
        wh[(size_t)o*CONVK + k*CC + tid] = __float2half(scale * vv[k]);
}

// ---------------- qkv GEMM -----------------------------------------------------
__global__ void __launch_bounds__(256, 3) k_qkv_mma() {
    extern __shared__ __align__(128) char smem[];
    int m0 = blockIdx.x * 128;
    int n0 = blockIdx.y * 64;
    int tid = threadIdx.x;
    int wid = tid >> 5, lane = tid & 31;
    int warp_m = wid & 3, warp_n = wid >> 2;
    int g = lane >> 2, tg = lane & 3;
    u32 sbase = smem_u32(smem);
    int arow = tid >> 1, ahalf = tid & 1;
    int brow = tid >> 2, bq4 = tid & 3;
    LDSM_OFFS()

    float acc[2][4][4];
#pragma unroll
    for (int a = 0; a < 2; a++)
#pragma unroll
        for (int c = 0; c < 4; c++)
#pragma unroll
            for (int d = 0; d < 4; d++) acc[a][c][d] = 0.f;

#define ISSUE(cc, st) do {                                                    \
        size_t ga = (size_t)(m0 + arow)*CC + (cc)*32 + ahalf*16;              \
        cp16((st) + SWZ(arow, ahalf*2),     g_xth + ga,     true);            \
        cp16((st) + SWZ(arow, ahalf*2 + 1), g_xth + ga + 8, true);            \
        size_t gb = (size_t)(n0 + brow)*CC + (cc)*32 + bq4*8;                 \
        cp16((st) + A_MATB + SWZ(brow, bq4), g_wcbh + gb, true);              \
    } while (0)

    MMA_MAINLOOP(8)
#undef ISSUE

    int b = m0 >> 10, t0 = m0 & 1023;
#pragma unroll
    for (int mt = 0; mt < 2; mt++) {
        int mr = warp_m*32 + mt*16 + g;
#pragma unroll
        for (int nt = 0; nt < 4; nt++) {
            int n = n0 + warp_n*32 + nt*8 + tg*2;
            float* c = acc[mt][nt];
            float v00 = c[0] + g_bcat[n],   v01 = c[1] + g_bcat[n+1];
            float v10 = c[2] + g_bcat[n],   v11 = c[3] + g_bcat[n+1];
            if (n < 128) {
                __half* ph = (n < 64) ? g_qh : g_kh;
                int nn = n & 63;
                size_t i_lo = (size_t)(m0 + mr)*64 + nn;
                size_t i_hi = (size_t)(m0 + mr + 8)*64 + nn;
                *(__half2*)&ph[i_lo] =
                    __halves2half2(__float2half(v00), __float2half(v01));
                *(__half2*)&ph[i_hi] =
                    __halves2half2(__float2half(v10), __float2half(v11));
            } else {
                int cch = n - 128;
                int t_lo = t0 + mr, t_hi = t_lo + 8;
                size_t b00 = ((size_t)b*CC + cch)*TT;
                g_vth[b00 + t_lo]      = __float2half(v00);
                g_vth[b00 + t_hi]      = __float2half(v10);
                g_vth[b00 + TT + t_lo] = __float2half(v01);
                g_vth[b00 + TT + t_hi] = __float2half(v11);
            }
        }
    }
}

// --- scores GEMM: e[b][j][i] = exp(k.q/8) masked (fp16) + sum partials -------
__global__ void __launch_bounds__(256, 3) k_scores_mma() {
    int i0 = blockIdx.x * 64, j0 = blockIdx.y * 128, b = blockIdx.z;
    if (j0 > i0 + 63) return;
    extern __shared__ __align__(128) char smem[];
    __shared__ float s_sum[128][2];
    int tid = threadIdx.x;
    int wid = tid >> 5, lane = tid & 31;
    int warp_m = wid & 3, warp_n = wid >> 2;
    int g = lane >> 2, tg = lane & 3;
    u32 sbase = smem_u32(smem);
    int arow = tid >> 1, ahalf = tid & 1;
    int brow = tid >> 2, bq4 = tid & 3;
    LDSM_OFFS()

    float acc[2][4][4];
#pragma unroll
    for (int a = 0; a < 2; a++)
#pragma unroll
        for (int c = 0; c < 4; c++)
#pragma unroll
            for (int d = 0; d < 4; d++) acc[a][c][d] = 0.f;

    const __half* Ahp = g_kh + (size_t)(b*TT + j0)*64;
    const __half* Bhp = g_qh + (size_t)(b*TT + i0)*64;

#define ISSUE(cc, st) do {                                                    \
        size_t ga = (size_t)arow*64 + (cc)*32 + ahalf*16;                     \
        cp16((st) + SWZ(arow, ahalf*2),     Ahp + ga,     true);              \
        cp16((st) + SWZ(arow, ahalf*2 + 1), Ahp + ga + 8, true);              \
        size_t gb = (size_t)brow*64 + (cc)*32 + bq4*8;                        \
        cp16((st) + A_MATB + SWZ(brow, bq4), Bhp + gb, true);                 \
    } while (0)

    MMA_MAINLOOP(2)
#undef ISSUE

    size_t base = (size_t)b*TT*TT;
    float psum[2];
#pragma unroll
    for (int mt = 0; mt < 2; mt++) {
        int j_lo = j0 + warp_m*32 + mt*16 + g;
        int j_hi = j_lo + 8;
        psum[0] = 0.f; psum[1] = 0.f;
#pragma unroll
        for (int nt = 0; nt < 4; nt++) {
            int i = i0 + warp_n*32 + nt*8 + tg*2;
            float* c = acc[mt][nt];
            float e0 = (i   >= j_lo) ? __expf(c[0]*0.125f) : 0.f;
            float e1 = (i+1 >= j_lo) ? __expf(c[1]*0.125f) : 0.f;
            float e2 = (i   >= j_hi) ? __expf(c[2]*0.125f) : 0.f;
            float e3 = (i+1 >= j_hi) ? __expf(c[3]*0.125f) : 0.f;
            *(__half2*)&g_e[base + (size_t)j_lo*TT + i] =
                __halves2half2(__float2half(e0), __float2half(e1));
            *(__half2*)&g_e[base + (size_t)j_hi*TT + i] =
                __halves2half2(__float2half(e2), __float2half(e3));
            psum[0] += e0 + e1;
            psum[1] += e2 + e3;
        }
        float p0 = psum[0], p1 = psum[1];
        p0 += __shfl_xor_sync(0xffffffffu, p0, 1);
        p0 += __shfl_xor_sync(0xffffffffu, p0, 2);
        p1 += __shfl_xor_sync(0xffffffffu, p1, 1);
        p1 += __shfl_xor_sync(0xffffffffu, p1, 2);
        if (tg == 0) {
            int rl = warp_m*32 + mt*16 + g;
            s_sum[rl][warp_n]     = p0;
            s_sum[rl + 8][warp_n] = p1;
        }
    }
    __syncthreads();
    if (tid < 128) {
        float s = s_sum[tid][0] + s_sum[tid][1];
        g_ssp[(size_t)(b*TT + j0 + tid)*16 + (i0 >> 6)] = s;
    }
}

// ---------------- rz[row] = 1 / sumexp (reduce ssp partials) -----------------
__global__ void k_rz() {
    int row = blockIdx.x * 256 + threadIdx.x;   // b*T + j
    int j = row & 1023;
    const float* p = &g_ssp[(size_t)row*16];
    float s = 0.f;
    for (int k = (j >> 6); k < 16; k++) s += p[k];
    g_rz[row] = 1.f / s;
}

// ------- attn transpose (fp16 in, fp16 out) + fused rowsum partials ----------
__global__ void __launch_bounds__(256) k_attn_t() {
    int i0 = blockIdx.x * 64, j0 = blockIdx.y * 64, b = blockIdx.z;
    if (j0 > i0) return;
    __shared__ float sm[64][65];
    __shared__ float s2[4][64];
    int tid = threadIdx.x;
    int il = tid & 63, jg = tid >> 6;
    size_t base = (size_t)b*TT*TT;
    float part = 0.f;
#pragma unroll 4
    for (int r = 0; r < 16; r++) {
        int j = j0 + jg*16 + r;
        float rz = g_rz[b*TT + j];
        float a = __half2float(g_e[base + (size_t)j*TT + i0 + il]) * rz;
        sm[jg*16 + r][il] = a;
        part += a;
    }
    s2[jg][il] = part;
    __syncthreads();
    int jl = tid & 63, ig = tid >> 6;
#pragma unroll 4
    for (int r = 0; r < 16; r++) {
        int i_local = ig*16 + r;
        size_t idx = ((size_t)b*TT + i0 + i_local)*TT + j0 + jl;
        g_ath[idx] = __float2half(sm[jl][i_local]);
    }
    if (tid < 64)
        g_rsp[((size_t)b*TT + i0 + tid)*16 + (j0 >> 6)] =
            s2[0][tid] + s2[1][tid] + s2[2][tid] + s2[3][tid];
}

// ---------------- weight_x = softmax_t(rowsum), rowsum fused -----------------
__global__ void k_wx() {
    int b = blockIdx.x, tid = threadIdx.x;
    __shared__ float sm[256];
    float v[4], e[4];
    float mx = -1e30f;
#pragma unroll
    for (int r = 0; r < 4; r++) {
        int il = tid + r*256;
        const float* p = &g_rsp[(size_t)(b*TT + il)*16];
        int ntile = il >> 6;
        float s = 0.f;
        for (int k = 0; k <= ntile; k++) s += p[k];
        v[r] = s;
        mx = fmaxf(mx, v[r]);
    }
    sm[tid] = mx; __syncthreads();
    for (int s = 128; s > 0; s >>= 1) {
        if (tid < s) sm[tid] = fmaxf(sm[tid], sm[tid+s]);
        __syncthreads();
    }
    mx = sm[0]; __syncthreads();
    float sum = 0.f;
#pragma unroll
    for (int r = 0; r < 4; r++) { e[r] = __expf(v[r] - mx); sum += e[r]; }
    sm[tid] = sum; __syncthreads();
    for (int s = 128; s > 0; s >>= 1) {
        if (tid < s) sm[tid] += sm[tid+s];
        __syncthreads();
    }
    float rz = 1.f / sm[0];
#pragma unroll
    for (int r = 0; r < 4; r++) g_wx[b*TT + tid + r*256] = e[r] * rz;
}

// ---------------- av GEMM: h1[i][c] = attn @ v, banded K ---------------------
__global__ void __launch_bounds__(256, 3) k_av_mma() {
    extern __shared__ __align__(128) char smem[];
    int m0 = blockIdx.x * 128;
    int n0 = blockIdx.y * 64;
    int b = m0 >> 10, t0 = m0 & 1023;
    int tid = threadIdx.x;
    int wid = tid >> 5, lane = tid & 31;
    int warp_m = wid & 3, warp_n = wid >> 2;
    int g = lane >> 2, tg = lane & 3;
    u32 sbase = smem_u32(smem);
    int arow = tid >> 1, ahalf = tid & 1;
    int brow = tid >> 2, bq4 = tid & 3;
    LDSM_OFFS()

    float acc[2][4][4];
#pragma unroll
    for (int a = 0; a < 2; a++)
#pragma unroll
        for (int c = 0; c < 4; c++)
#pragma unroll
            for (int d = 0; d < 4; d++) acc[a][c][d] = 0.f;

    const __half* Ahp = g_ath + ((size_t)b*TT + t0)*TT;
    const __half* Bhp = g_vth + ((size_t)b*CC + n0)*TT;
    int nch = (t0 + 128) >> 5;

#define ISSUE(cc, st) do {                                                    \
        size_t ga = (size_t)arow*TT + (cc)*32 + ahalf*16;                     \
        cp16((st) + SWZ(arow, ahalf*2),     Ahp + ga,     true);              \
        cp16((st) + SWZ(arow, ahalf*2 + 1), Ahp + ga + 8, true);              \
        size_t gb = (size_t)brow*TT + (cc)*32 + bq4*8;                        \
        cp16((st) + A_MATB + SWZ(brow, bq4), Bhp + gb, true);                 \
    } while (0)

    MMA_MAINLOOP(nch)
#undef ISSUE

#pragma unroll
    for (int mt = 0; mt < 2; mt++) {
        int m_lo = m0 + warp_m*32 + mt*16 + g;
#pragma unroll
        for (int nt = 0; nt < 4; nt++) {
            int n = n0 + warp_n*32 + nt*8 + tg*2;
            float* c = acc[mt][nt];
            size_t i_lo = (size_t)m_lo*CC + n;
            size_t i_hi = (size_t)(m_lo+8)*CC + n;
            *(__half2*)&g_h1h[i_lo] =
                __halves2half2(__float2half(c[0]), __float2half(c[1]));
            *(__half2*)&g_h1h[i_hi] =
                __halves2half2(__float2half(c[2]), __float2half(c[3]));
        }
    }
}

// ---------------- conv GEMM --------------------------------------------------
__global__ void __launch_bounds__(256, 3) k_conv_mma(int mode,
                                                     const float* __restrict__ bias,
                                                     const float* __restrict__ x,
                                                     float* __restrict__ outp) {
    extern __shared__ __align__(128) char smem[];
    const __half* Ahp = mode ? g_h2h  : g_h1h;
    const __half* Bhp = mode ? g_w2bh : g_w1bh;

    int m0 = blockIdx.x * 128;
    int n0 = blockIdx.y * 64;
    int b = m0 >> 10, t0 = m0 & 1023;
    int tid = threadIdx.x;
    int wid = tid >> 5, lane = tid & 31;
    int warp_m = wid & 3, warp_n = wid >> 2;
    int g = lane >> 2, tg = lane & 3;
    u32 sbase = smem_u32(smem);
    int arow = tid >> 1, ahalf = tid & 1;
    int brow = tid >> 2, bq4 = tid & 3;
    LDSM_OFFS()

    float acc[2][4][4];
#pragma unroll
    for (int a = 0; a < 2; a++)
#pragma unroll
        for (int c = 0; c < 4; c++)
#pragma unroll
            for (int d = 0; d < 4; d++) acc[a][c][d] = 0.f;

#define ISSUE(cc, st) do {                                                    \
        int koff = (cc) >> 3, i0c = ((cc) & 7) * 32;                          \
        int t = t0 + arow + koff - 2;                                         \
        bool ok = (t >= 0);                                                   \
        size_t ga = (size_t)(b*TT + t)*CC + i0c + ahalf*16;                   \
        cp16((st) + SWZ(arow, ahalf*2),     Ahp + ga,     ok);                \
        cp16((st) + SWZ(arow, ahalf*2 + 1), Ahp + ga + 8, ok);                \
        size_t gb = (size_t)(n0 + brow)*CONVK + (cc)*32 + bq4*8;              \
        cp16((st) + A_MATB + SWZ(brow, bq4), Bhp + gb, true);                 \
    } while (0)

    MMA_MAINLOOP(24)
#undef ISSUE

#pragma unroll
    for (int mt = 0; mt < 2; mt++) {
        int t_lo = t0 + warp_m*32 + mt*16 + g;
        int t_hi = t_lo + 8;
        if (mode == 0) {
#pragma unroll
            for (int nt = 0; nt < 4; nt++) {
                int n = n0 + warp_n*32 + nt*8 + tg*2;
                float b0 = bias[n], b1 = bias[n+1];
                float* c = acc[mt][nt];
                float v0 = fmaxf(c[0] + b0, 0.f);
                float v1 = fmaxf(c[1] + b1, 0.f);
                float v2 = fmaxf(c[2] + b0, 0.f);
                float v3 = fmaxf(c[3] + b1, 0.f);
                size_t i_lo = (size_t)(b*TT + t_lo)*CC + n;
                size_t i_hi = (size_t)(b*TT + t_hi)*CC + n;
                *(__half2*)&g_h2h[i_lo] =
                    __halves2half2(__float2half(v0), __float2half(v1));
                *(__half2*)&g_h2h[i_hi] =
                    __halves2half2(__float2half(v2), __float2half(v3));
            }
        } else {
            float w_lo = 1.f + g_wx[b*TT + t_lo];
            float w_hi = 1.f + g_wx[b*TT + t_hi];
#pragma unroll
            for (int nt = 0; nt < 4; nt++) {
                int n = n0 + warp_n*32 + nt*8 + tg*2;
                float b0 = bias[n], b1 = bias[n+1];
                float* c = acc[mt][nt];
                size_t o00 = ((size_t)b*CC + n)*TT + t_lo;
                size_t o10 = o00 + TT;
                size_t o01 = o00 + 8;
                size_t o11 = o10 + 8;
                outp[o00] = fmaxf(fmaxf(c[0] + b0, 0.f) + x[o00]*w_lo, 0.f);
                outp[o10] = fmaxf(fmaxf(c[1] + b1, 0.f) + x[o10]*w_lo, 0.f);
                outp[o01] = fmaxf(fmaxf(c[2] + b0, 0.f) + x[o01]*w_hi, 0.f);
                outp[o11] = fmaxf(fmaxf(c[3] + b1, 0.f) + x[o11]*w_hi, 0.f);
            }
        }
    }
}

// ---------------- launch ------------------------------------------------------
extern "C" void kernel_launch(void* const* d_in, const int* in_sizes, int n_in,
                              void* d_out, int out_size) {
    const float* x  = (const float*)d_in[0];
    const float* wq = (const float*)d_in[1];
    const float* bq = (const float*)d_in[2];
    const float* wk = (const float*)d_in[3];
    const float* bk = (const float*)d_in[4];
    const float* wv = (const float*)d_in[5];
    const float* bv = (const float*)d_in[6];
    const float* v1 = (const float*)d_in[7];
    const float* g1 = (const float*)d_in[8];
    const float* b1 = (const float*)d_in[9];
    const float* v2 = (const float*)d_in[10];
    const float* g2 = (const float*)d_in[11];
    const float* b2 = (const float*)d_in[12];
    float* out = (float*)d_out;

    static int smset = 0;
    if (!smset) {
        cudaFuncSetAttribute(k_qkv_mma,    cudaFuncAttributeMaxDynamicSharedMemorySize, MMA_SMEM);
        cudaFuncSetAttribute(k_scores_mma, cudaFuncAttributeMaxDynamicSharedMemorySize, MMA_SMEM);
        cudaFuncSetAttribute(k_av_mma,     cudaFuncAttributeMaxDynamicSharedMemorySize, MMA_SMEM);
        cudaFuncSetAttribute(k_conv_mma,   cudaFuncAttributeMaxDynamicSharedMemorySize, MMA_SMEM);
        smset = 1;
    }

    k_prep_xt<<<dim3(TT/32, CC/32, BB), 256>>>(x);
    k_prep_wcat<<<QKVW, 256>>>(wq, bq, wk, bk, wv, bv);
    k_prep_convw<<<512, 256>>>(v1, g1, v2, g2);
    k_qkv_mma<<<dim3(MT/128, QKVW/64), 256, MMA_SMEM>>>();
    k_scores_mma<<<dim3(16, 8, BB), 256, MMA_SMEM>>>();
    k_rz<<<MT/256, 256>>>();
    k_attn_t<<<dim3(16, 16, BB), 256>>>();
    k_wx<<<BB, 256>>>();
    k_av_mma<<<dim3(MT/128, CC/64), 256, MMA_SMEM>>>();
    k_conv_mma<<<dim3(MT/128, CC/64), 256, MMA_SMEM>>>(0, b1, x, out);
    k_conv_mma<<<dim3(MT/128, CC/64), 256, MMA_SMEM>>>(1, b2, x, out);
}

// round 16
// speedup vs baseline: 1.1480x; 1.0274x over previous
#include <cuda_runtime.h>
#include <cuda_fp16.h>
#include <cstdint>

#define BB 32
#define CC 256
#define TT 1024
#define QKVW 384
#define MT (BB*TT)
#define CONVK 768

typedef uint32_t u32;

// ---------------- scratch (device globals; zero-initialized BSS) -------------
__device__ float g_bcat[QKVW];
__device__ float g_ssp[(size_t)MT*16];       // sumexp partials per i-tile
__device__ float g_rz[MT];
__device__ float g_rsp[(size_t)MT*16];       // rowsum partials per j-tile
__device__ float g_wx[MT];
// plain fp16 operands
__device__ __align__(16) __half g_xth[(size_t)MT*CC];   // x^T [t][c]
__device__ __align__(16) __half g_wcbh[QKVW*CC];        // wcat^T [n][c]
__device__ __align__(16) __half g_qh[(size_t)MT*64];
__device__ __align__(16) __half g_kh[(size_t)MT*64];
__device__ __align__(16) __half g_vth[(size_t)BB*CC*TT]; // v^T [b][c][t]
__device__ __align__(16) __half g_e[(size_t)BB*TT*TT];   // e=exp(s) [b][j][i]
__device__ __align__(16) __half g_ath[(size_t)BB*TT*TT]; // attn [b][i][j]
__device__ __align__(16) __half g_h1h[(size_t)MT*CC];
__device__ __align__(16) __half g_h2h[(size_t)MT*CC];
__device__ __align__(16) __half g_w1bh[CC*CONVK];
__device__ __align__(16) __half g_w2bh[CC*CONVK];

// ---------------- helpers ----------------------------------------------------
__device__ __forceinline__ u32 smem_u32(const void* p) {
    u32 a;
    asm("{ .reg .u64 t; cvta.to.shared.u64 t, %1; cvt.u32.u64 %0, t; }"
        : "=r"(a) : "l"(p));
    return a;
}
__device__ __forceinline__ void cp16(u32 dst, const void* src, bool ok) {
    int sz = ok ? 16 : 0;
    asm volatile("cp.async.cg.shared.global [%0], [%1], 16, %2;"
                 :: "r"(dst), "l"(src), "r"(sz) : "memory");
}
#define CP_COMMIT() asm volatile("cp.async.commit_group;" ::: "memory")
#define CP_WAIT2()  asm volatile("cp.async.wait_group 2;" ::: "memory")
#define CP_WAIT0()  asm volatile("cp.async.wait_group 0;" ::: "memory")

__device__ __forceinline__ void mma16816(float c[4], const u32 a[4], const u32 b[2]) {
    asm volatile(
        "mma.sync.aligned.m16n8k16.row.col.f32.f16.f16.f32 "
        "{%0,%1,%2,%3}, {%4,%5,%6,%7}, {%8,%9}, {%0,%1,%2,%3};"
        : "+f"(c[0]), "+f"(c[1]), "+f"(c[2]), "+f"(c[3])
        : "r"(a[0]), "r"(a[1]), "r"(a[2]), "r"(a[3]), "r"(b[0]), "r"(b[1]));
}
__device__ __forceinline__ void ldsm4(u32& r0, u32& r1, u32& r2, u32& r3, u32 addr) {
    asm volatile("ldmatrix.sync.aligned.m8n8.x4.shared.b16 {%0,%1,%2,%3}, [%4];"
                 : "=r"(r0), "=r"(r1), "=r"(r2), "=r"(r3) : "r"(addr));
}

// ---- stage geometry (swizzled, no padding): rows of 64B, 16B chunk XOR ------
#define SWZ(row, chunk) ((u32)((row)*64 + ((((chunk) ^ (((row) >> 1) & 3))) << 4)))
#define A_MATB 8192            // 128 rows * 64 B
#define B_MATB 4096            // 64 rows * 64 B
#define STG (A_MATB + B_MATB)  // 12288 (A, B)
#define NSTAGE 4
#define MMA_SMEM (NSTAGE*STG)  // 49152 -> 3 CTAs/SM

// one K=32 chunk via ldmatrix: warp tile 32(M) x 32(N), plain fp16
__device__ __forceinline__ void mma_chunk4(u32 base, u32 aA0, u32 aA1,
                                           u32 bB0, u32 bB1,
                                           float acc[2][4][4]) {
#pragma unroll
    for (int ks = 0; ks < 2; ks++) {
        u32 aoffk = ks ? aA1 : aA0;
        u32 boffk = ks ? bB1 : bB0;
        u32 ah[2][4];
#pragma unroll
        for (int mt = 0; mt < 2; mt++) {
            u32 ad = base + aoffk + mt*1024;
            ldsm4(ah[mt][0], ah[mt][1], ah[mt][2], ah[mt][3], ad);
        }
        u32 bh[4][2];
#pragma unroll
        for (int pr = 0; pr < 2; pr++) {
            u32 bd = base + A_MATB + boffk + pr*1024;
            u32 r0, r1, r2, r3;
            ldsm4(r0, r1, r2, r3, bd);
            bh[2*pr][0] = r0; bh[2*pr][1] = r1;
            bh[2*pr+1][0] = r2; bh[2*pr+1][1] = r3;
        }
#pragma unroll
        for (int mt = 0; mt < 2; mt++)
#pragma unroll
            for (int nt = 0; nt < 4; nt++)
                mma16816(acc[mt][nt], ah[mt], bh[nt]);
    }
}

// per-warp ldmatrix swizzled base offsets (ks=0 / ks=1 pre-XORed)
#define LDSM_OFFS()                                                           \
    u32 mx = (lane >> 1) & 3;                                                 \
    u32 rA = (u32)(warp_m*32 + (lane & 15));                                  \
    u32 cAb = (u32)(lane >> 4);                                               \
    u32 aA0 = rA*64 + ((cAb ^ mx) << 4);                                      \
    u32 aA1 = rA*64 + (((cAb ^ 2) ^ mx) << 4);                                \
    u32 rB = (u32)(warp_n*32 + ((lane >> 4) << 3) + (lane & 7));              \
    u32 cBb = (u32)((lane >> 3) & 1);                                         \
    u32 bB0 = rB*64 + ((cBb ^ mx) << 4);                                      \
    u32 bB1 = rB*64 + (((cBb ^ 2) ^ mx) << 4);

// 4-stage mainloop, one sync per chunk, up to 3 loads in flight.
#define MMA_MAINLOOP(NCH)                                                     \
    { ISSUE(0, sbase); } CP_COMMIT();                                         \
    if (1 < (NCH)) { ISSUE(1, sbase + STG); } CP_COMMIT();                    \
    if (2 < (NCH)) { ISSUE(2, sbase + 2*STG); } CP_COMMIT();                  \
    for (int cc = 0; cc < (NCH); cc++) {                                      \
        u32 sb = sbase + (u32)(cc % NSTAGE)*STG;                              \
        if (cc + 1 < (NCH)) { CP_WAIT2(); } else { CP_WAIT0(); }              \
        __syncthreads();                                                      \
        if (cc + 3 < (NCH)) {                                                 \
            ISSUE(cc + 3, sbase + (u32)((cc + 3) % NSTAGE)*STG);              \
        }                                                                     \
        CP_COMMIT();                                                          \
        mma_chunk4(sb, aA0, aA1, bB0, bB1, acc);                              \
    }

// ---------------- prep: transpose x to fp16 [t][c] ---------------------------
__global__ void k_prep_xt(const float* __restrict__ x) {
    __shared__ float sm[32][33];
    int t0 = blockIdx.x * 32, c0 = blockIdx.y * 32, b = blockIdx.z;
    int lane = threadIdx.x & 31, grp = threadIdx.x >> 5;
#pragma unroll
    for (int r = 0; r < 4; r++) {
        int c = grp + r*8;
        sm[c][lane] = x[((size_t)b*CC + c0 + c)*TT + t0 + lane];
    }
    __syncthreads();
#pragma unroll
    for (int r = 0; r < 4; r++) {
        int t = grp + r*8;
        size_t idx = (size_t)(b*TT + t0 + t)*CC + c0 + lane;
        g_xth[idx] = __float2half(sm[lane][t]);
    }
}

// ---------------- prep: wcat^T (fp16) + bcat ---------------------------------
__global__ void k_prep_wcat(const float* __restrict__ wq, const float* __restrict__ bq,
                            const float* __restrict__ wk, const float* __restrict__ bk,
                            const float* __restrict__ wv, const float* __restrict__ bv) {
    int n = blockIdx.x;
    int c = threadIdx.x;
    float w;
    if (n < 64)       w = wq[c*64 + n];
    else if (n < 128) w = wk[c*64 + (n-64)];
    else              w = wv[c*256 + (n-128)];
    g_wcbh[n*CC + c] = __float2half(w);
    if (c == 0)
        g_bcat[n] = (n < 64) ? bq[n] : (n < 128) ? bk[n-64] : bv[n-128];
}

// ---------------- prep: weight-norm conv weights (fp16) ----------------------
__global__ void k_prep_convw(const float* __restrict__ v1, const float* __restrict__ g1,
                             const float* __restrict__ v2, const float* __restrict__ g2) {
    int layer = blockIdx.x >> 8;
    int o = blockIdx.x & 255;
    const float* v = layer ? v2 : v1;
    const float* g = layer ? g2 : g1;
    __half* wh = layer ? g_w2bh : g_w1bh;
    int tid = threadIdx.x;
    float vv[3];
    float part = 0.f;
#pragma unroll
    for (int k = 0; k < 3; k++) {
        vv[k] = v[((size_t)o*CC + tid)*3 + k];
        part += vv[k]*vv[k];
    }
    __shared__ float sm[256];
    sm[tid] = part; __syncthreads();
    for (int s = 128; s > 0; s >>= 1) {
        if (tid < s) sm[tid] += sm[tid+s];
        __syncthreads();
    }
    float scale = g[o] * rsqrtf(sm[0]);
#pragma unroll
    for (int k = 0; k < 3; k++)
        wh[(size_t)o*CONVK + k*CC + tid] = __float2half(scale * vv[k]);
}

// ---------------- qkv GEMM -----------------------------------------------------
__global__ void __launch_bounds__(256, 3) k_qkv_mma() {
    extern __shared__ __align__(128) char smem[];
    int m0 = blockIdx.x * 128;
    int n0 = blockIdx.y * 64;
    int tid = threadIdx.x;
    int wid = tid >> 5, lane = tid & 31;
    int warp_m = wid & 3, warp_n = wid >> 2;
    int g = lane >> 2, tg = lane & 3;
    u32 sbase = smem_u32(smem);
    int arow = tid >> 1, ahalf = tid & 1;
    int brow = tid >> 2, bq4 = tid & 3;
    LDSM_OFFS()

    float acc[2][4][4];
#pragma unroll
    for (int a = 0; a < 2; a++)
#pragma unroll
        for (int c = 0; c < 4; c++)
#pragma unroll
            for (int d = 0; d < 4; d++) acc[a][c][d] = 0.f;

#define ISSUE(cc, st) do {                                                    \
        size_t ga = (size_t)(m0 + arow)*CC + (cc)*32 + ahalf*16;              \
        cp16((st) + SWZ(arow, ahalf*2),     g_xth + ga,     true);            \
        cp16((st) + SWZ(arow, ahalf*2 + 1), g_xth + ga + 8, true);            \
        size_t gb = (size_t)(n0 + brow)*CC + (cc)*32 + bq4*8;                 \
        cp16((st) + A_MATB + SWZ(brow, bq4), g_wcbh + gb, true);              \
    } while (0)

    MMA_MAINLOOP(8)
#undef ISSUE

    int b = m0 >> 10, t0 = m0 & 1023;
#pragma unroll
    for (int mt = 0; mt < 2; mt++) {
        int mr = warp_m*32 + mt*16 + g;
#pragma unroll
        for (int nt = 0; nt < 4; nt++) {
            int n = n0 + warp_n*32 + nt*8 + tg*2;
            float* c = acc[mt][nt];
            float v00 = c[0] + g_bcat[n],   v01 = c[1] + g_bcat[n+1];
            float v10 = c[2] + g_bcat[n],   v11 = c[3] + g_bcat[n+1];
            if (n < 128) {
                __half* ph = (n < 64) ? g_qh : g_kh;
                int nn = n & 63;
                size_t i_lo = (size_t)(m0 + mr)*64 + nn;
                size_t i_hi = (size_t)(m0 + mr + 8)*64 + nn;
                *(__half2*)&ph[i_lo] =
                    __halves2half2(__float2half(v00), __float2half(v01));
                *(__half2*)&ph[i_hi] =
                    __halves2half2(__float2half(v10), __float2half(v11));
            } else {
                int cch = n - 128;
                int t_lo = t0 + mr, t_hi = t_lo + 8;
                size_t b00 = ((size_t)b*CC + cch)*TT;
                g_vth[b00 + t_lo]      = __float2half(v00);
                g_vth[b00 + t_hi]      = __float2half(v10);
                g_vth[b00 + TT + t_lo] = __float2half(v01);
                g_vth[b00 + TT + t_hi] = __float2half(v11);
            }
        }
    }
}

// --- scores GEMM: e[b][j][i] = exp(k.q/8) masked (fp16) + sum partials -------
__global__ void __launch_bounds__(256, 3) k_scores_mma() {
    int i0 = blockIdx.x * 64, j0 = blockIdx.y * 128, b = blockIdx.z;
    if (j0 > i0 + 63) return;
    extern __shared__ __align__(128) char smem[];
    __shared__ float s_sum[128][2];
    int tid = threadIdx.x;
    int wid = tid >> 5, lane = tid & 31;
    int warp_m = wid & 3, warp_n = wid >> 2;
    int g = lane >> 2, tg = lane & 3;
    u32 sbase = smem_u32(smem);
    int arow = tid >> 1, ahalf = tid & 1;
    int brow = tid >> 2, bq4 = tid & 3;
    LDSM_OFFS()

    float acc[2][4][4];
#pragma unroll
    for (int a = 0; a < 2; a++)
#pragma unroll
        for (int c = 0; c < 4; c++)
#pragma unroll
            for (int d = 0; d < 4; d++) acc[a][c][d] = 0.f;

    const __half* Ahp = g_kh + (size_t)(b*TT + j0)*64;
    const __half* Bhp = g_qh + (size_t)(b*TT + i0)*64;

#define ISSUE(cc, st) do {                                                    \
        size_t ga = (size_t)arow*64 + (cc)*32 + ahalf*16;                     \
        cp16((st) + SWZ(arow, ahalf*2),     Ahp + ga,     true);              \
        cp16((st) + SWZ(arow, ahalf*2 + 1), Ahp + ga + 8, true);              \
        size_t gb = (size_t)brow*64 + (cc)*32 + bq4*8;                        \
        cp16((st) + A_MATB + SWZ(brow, bq4), Bhp + gb, true);                 \
    } while (0)

    MMA_MAINLOOP(2)
#undef ISSUE

    size_t base = (size_t)b*TT*TT;
    float psum[2];
#pragma unroll
    for (int mt = 0; mt < 2; mt++) {
        int j_lo = j0 + warp_m*32 + mt*16 + g;
        int j_hi = j_lo + 8;
        psum[0] = 0.f; psum[1] = 0.f;
#pragma unroll
        for (int nt = 0; nt < 4; nt++) {
            int i = i0 + warp_n*32 + nt*8 + tg*2;
            float* c = acc[mt][nt];
            float e0 = (i   >= j_lo) ? __expf(c[0]*0.125f) : 0.f;
            float e1 = (i+1 >= j_lo) ? __expf(c[1]*0.125f) : 0.f;
            float e2 = (i   >= j_hi) ? __expf(c[2]*0.125f) : 0.f;
            float e3 = (i+1 >= j_hi) ? __expf(c[3]*0.125f) : 0.f;
            *(__half2*)&g_e[base + (size_t)j_lo*TT + i] =
                __halves2half2(__float2half(e0), __float2half(e1));
            *(__half2*)&g_e[base + (size_t)j_hi*TT + i] =
                __halves2half2(__float2half(e2), __float2half(e3));
            psum[0] += e0 + e1;
            psum[1] += e2 + e3;
        }
        float p0 = psum[0], p1 = psum[1];
        p0 += __shfl_xor_sync(0xffffffffu, p0, 1);
        p0 += __shfl_xor_sync(0xffffffffu, p0, 2);
        p1 += __shfl_xor_sync(0xffffffffu, p1, 1);
        p1 += __shfl_xor_sync(0xffffffffu, p1, 2);
        if (tg == 0) {
            int rl = warp_m*32 + mt*16 + g;
            s_sum[rl][warp_n]     = p0;
            s_sum[rl + 8][warp_n] = p1;
        }
    }
    __syncthreads();
    if (tid < 128) {
        float s = s_sum[tid][0] + s_sum[tid][1];
        g_ssp[(size_t)(b*TT + j0 + tid)*16 + (i0 >> 6)] = s;
    }
}

// ---------------- rz[row] = 1 / sumexp (reduce ssp partials) -----------------
__global__ void k_rz() {
    int row = blockIdx.x * 256 + threadIdx.x;   // b*T + j
    int j = row & 1023;
    const float* p = &g_ssp[(size_t)row*16];
    float s = 0.f;
    for (int k = (j >> 6); k < 16; k++) s += p[k];
    g_rz[row] = 1.f / s;
}

// ------- attn transpose (fp16 in, fp16 out) + fused rowsum partials ----------
__global__ void __launch_bounds__(256) k_attn_t() {
    int i0 = blockIdx.x * 64, j0 = blockIdx.y * 64, b = blockIdx.z;
    if (j0 > i0) return;
    __shared__ float sm[64][65];
    __shared__ float s2[4][64];
    int tid = threadIdx.x;
    int il = tid & 63, jg = tid >> 6;
    size_t base = (size_t)b*TT*TT;
    float part = 0.f;
#pragma unroll 4
    for (int r = 0; r < 16; r++) {
        int j = j0 + jg*16 + r;
        float rz = g_rz[b*TT + j];
        float a = __half2float(g_e[base + (size_t)j*TT + i0 + il]) * rz;
        sm[jg*16 + r][il] = a;
        part += a;
    }
    s2[jg][il] = part;
    __syncthreads();
    int jl = tid & 63, ig = tid >> 6;
#pragma unroll 4
    for (int r = 0; r < 16; r++) {
        int i_local = ig*16 + r;
        size_t idx = ((size_t)b*TT + i0 + i_local)*TT + j0 + jl;
        g_ath[idx] = __float2half(sm[jl][i_local]);
    }
    if (tid < 64)
        g_rsp[((size_t)b*TT + i0 + tid)*16 + (j0 >> 6)] =
            s2[0][tid] + s2[1][tid] + s2[2][tid] + s2[3][tid];
}

// ---------------- weight_x = softmax_t(rowsum), rowsum fused -----------------
__global__ void k_wx() {
    int b = blockIdx.x, tid = threadIdx.x;
    __shared__ float sm[256];
    float v[4], e[4];
    float mx = -1e30f;
#pragma unroll
    for (int r = 0; r < 4; r++) {
        int il = tid + r*256;
        const float* p = &g_rsp[(size_t)(b*TT + il)*16];
        int ntile = il >> 6;
        float s = 0.f;
        for (int k = 0; k <= ntile; k++) s += p[k];
        v[r] = s;
        mx = fmaxf(mx, v[r]);
    }
    sm[tid] = mx; __syncthreads();
    for (int s = 128; s > 0; s >>= 1) {
        if (tid < s) sm[tid] = fmaxf(sm[tid], sm[tid+s]);
        __syncthreads();
    }
    mx = sm[0]; __syncthreads();
    float sum = 0.f;
#pragma unroll
    for (int r = 0; r < 4; r++) { e[r] = __expf(v[r] - mx); sum += e[r]; }
    sm[tid] = sum; __syncthreads();
    for (int s = 128; s > 0; s >>= 1) {
        if (tid < s) sm[tid] += sm[tid+s];
        __syncthreads();
    }
    float rz = 1.f / sm[0];
#pragma unroll
    for (int r = 0; r < 4; r++) g_wx[b*TT + tid + r*256] = e[r] * rz;
}

// ---------------- av GEMM: h1[i][c] = attn @ v, banded K ---------------------
__global__ void __launch_bounds__(256, 3) k_av_mma() {
    extern __shared__ __align__(128) char smem[];
    int m0 = blockIdx.x * 128;
    int n0 = blockIdx.y * 64;
    int b = m0 >> 10, t0 = m0 & 1023;
    int tid = threadIdx.x;
    int wid = tid >> 5, lane = tid & 31;
    int warp_m = wid & 3, warp_n = wid >> 2;
    int g = lane >> 2, tg = lane & 3;
    u32 sbase = smem_u32(smem);
    int arow = tid >> 1, ahalf = tid & 1;
    int brow = tid >> 2, bq4 = tid & 3;
    LDSM_OFFS()

    float acc[2][4][4];
#pragma unroll
    for (int a = 0; a < 2; a++)
#pragma unroll
        for (int c = 0; c < 4; c++)
#pragma unroll
            for (int d = 0; d < 4; d++) acc[a][c][d] = 0.f;

    const __half* Ahp = g_ath + ((size_t)b*TT + t0)*TT;
    const __half* Bhp = g_vth + ((size_t)b*CC + n0)*TT;
    int nch = (t0 + 128) >> 5;

#define ISSUE(cc, st) do {                                                    \
        size_t ga = (size_t)arow*TT + (cc)*32 + ahalf*16;                     \
        cp16((st) + SWZ(arow, ahalf*2),     Ahp + ga,     true);              \
        cp16((st) + SWZ(arow, ahalf*2 + 1), Ahp + ga + 8, true);              \
        size_t gb = (size_t)brow*TT + (cc)*32 + bq4*8;                        \
        cp16((st) + A_MATB + SWZ(brow, bq4), Bhp + gb, true);                 \
    } while (0)

    MMA_MAINLOOP(nch)
#undef ISSUE

#pragma unroll
    for (int mt = 0; mt < 2; mt++) {
        int m_lo = m0 + warp_m*32 + mt*16 + g;
#pragma unroll
        for (int nt = 0; nt < 4; nt++) {
            int n = n0 + warp_n*32 + nt*8 + tg*2;
            float* c = acc[mt][nt];
            size_t i_lo = (size_t)m_lo*CC + n;
            size_t i_hi = (size_t)(m_lo+8)*CC + n;
            *(__half2*)&g_h1h[i_lo] =
                __halves2half2(__float2half(c[0]), __float2half(c[1]));
            *(__half2*)&g_h1h[i_hi] =
                __halves2half2(__float2half(c[2]), __float2half(c[3]));
        }
    }
}

// ---------------- conv GEMM --------------------------------------------------
__global__ void __launch_bounds__(256, 3) k_conv_mma(int mode,
                                                     const float* __restrict__ bias,
                                                     const float* __restrict__ x,
                                                     float* __restrict__ outp) {
    extern __shared__ __align__(128) char smem[];
    const __half* Ahp = mode ? g_h2h  : g_h1h;
    const __half* Bhp = mode ? g_w2bh : g_w1bh;

    int m0 = blockIdx.x * 128;
    int n0 = blockIdx.y * 64;
    int b = m0 >> 10, t0 = m0 & 1023;
    int tid = threadIdx.x;
    int wid = tid >> 5, lane = tid & 31;
    int warp_m = wid & 3, warp_n = wid >> 2;
    int g = lane >> 2, tg = lane & 3;
    u32 sbase = smem_u32(smem);
    int arow = tid >> 1, ahalf = tid & 1;
    int brow = tid >> 2, bq4 = tid & 3;
    LDSM_OFFS()

    float acc[2][4][4];
#pragma unroll
    for (int a = 0; a < 2; a++)
#pragma unroll
        for (int c = 0; c < 4; c++)
#pragma unroll
            for (int d = 0; d < 4; d++) acc[a][c][d] = 0.f;

#define ISSUE(cc, st) do {                                                    \
        int koff = (cc) >> 3, i0c = ((cc) & 7) * 32;                          \
        int t = t0 + arow + koff - 2;                                         \
        bool ok = (t >= 0);                                                   \
        size_t ga = (size_t)(b*TT + t)*CC + i0c + ahalf*16;                   \
        cp16((st) + SWZ(arow, ahalf*2),     Ahp + ga,     ok);                \
        cp16((st) + SWZ(arow, ahalf*2 + 1), Ahp + ga + 8, ok);                \
        size_t gb = (size_t)(n0 + brow)*CONVK + (cc)*32 + bq4*8;              \
        cp16((st) + A_MATB + SWZ(brow, bq4), Bhp + gb, true);                 \
    } while (0)

    MMA_MAINLOOP(24)
#undef ISSUE

#pragma unroll
    for (int mt = 0; mt < 2; mt++) {
        int t_lo = t0 + warp_m*32 + mt*16 + g;
        int t_hi = t_lo + 8;
        if (mode == 0) {
#pragma unroll
            for (int nt = 0; nt < 4; nt++) {
                int n = n0 + warp_n*32 + nt*8 + tg*2;
                float b0 = bias[n], b1 = bias[n+1];
                float* c = acc[mt][nt];
                float v0 = fmaxf(c[0] + b0, 0.f);
                float v1 = fmaxf(c[1] + b1, 0.f);
                float v2 = fmaxf(c[2] + b0, 0.f);
                float v3 = fmaxf(c[3] + b1, 0.f);
                size_t i_lo = (size_t)(b*TT + t_lo)*CC + n;
                size_t i_hi = (size_t)(b*TT + t_hi)*CC + n;
                *(__half2*)&g_h2h[i_lo] =
                    __halves2half2(__float2half(v0), __float2half(v1));
                *(__half2*)&g_h2h[i_hi] =
                    __halves2half2(__float2half(v2), __float2half(v3));
            }
        } else {
            float w_lo = 1.f + g_wx[b*TT + t_lo];
            float w_hi = 1.f + g_wx[b*TT + t_hi];
#pragma unroll
            for (int nt = 0; nt < 4; nt++) {
                int n = n0 + warp_n*32 + nt*8 + tg*2;
                float b0 = bias[n], b1 = bias[n+1];
                float* c = acc[mt][nt];
                size_t o00 = ((size_t)b*CC + n)*TT + t_lo;
                size_t o10 = o00 + TT;
                size_t o01 = o00 + 8;
                size_t o11 = o10 + 8;
                outp[o00] = fmaxf(fmaxf(c[0] + b0, 0.f) + x[o00]*w_lo, 0.f);
                outp[o10] = fmaxf(fmaxf(c[1] + b1, 0.f) + x[o10]*w_lo, 0.f);
                outp[o01] = fmaxf(fmaxf(c[2] + b0, 0.f) + x[o01]*w_hi, 0.f);
                outp[o11] = fmaxf(fmaxf(c[3] + b1, 0.f) + x[o11]*w_hi, 0.f);
            }
        }
    }
}

// ---------------- launch ------------------------------------------------------
extern "C" void kernel_launch(void* const* d_in, const int* in_sizes, int n_in,
                              void* d_out, int out_size) {
    const float* x  = (const float*)d_in[0];
    const float* wq = (const float*)d_in[1];
    const float* bq = (const float*)d_in[2];
    const float* wk = (const float*)d_in[3];
    const float* bk = (const float*)d_in[4];
    const float* wv = (const float*)d_in[5];
    const float* bv = (const float*)d_in[6];
    const float* v1 = (const float*)d_in[7];
    const float* g1 = (const float*)d_in[8];
    const float* b1 = (const float*)d_in[9];
    const float* v2 = (const float*)d_in[10];
    const float* g2 = (const float*)d_in[11];
    const float* b2 = (const float*)d_in[12];
    float* out = (float*)d_out;

    static int smset = 0;
    if (!smset) {
        cudaFuncSetAttribute(k_qkv_mma,    cudaFuncAttributeMaxDynamicSharedMemorySize, MMA_SMEM);
        cudaFuncSetAttribute(k_scores_mma, cudaFuncAttributeMaxDynamicSharedMemorySize, MMA_SMEM);
        cudaFuncSetAttribute(k_av_mma,     cudaFuncAttributeMaxDynamicSharedMemorySize, MMA_SMEM);
        cudaFuncSetAttribute(k_conv_mma,   cudaFuncAttributeMaxDynamicSharedMemorySize, MMA_SMEM);
        smset = 1;
    }

    k_prep_xt<<<dim3(TT/32, CC/32, BB), 256>>>(x);
    k_prep_wcat<<<QKVW, 256>>>(wq, bq, wk, bk, wv, bv);
    k_prep_convw<<<512, 256>>>(v1, g1, v2, g2);
    k_qkv_mma<<<dim3(MT/128, QKVW/64), 256, MMA_SMEM>>>();
    k_scores_mma<<<dim3(16, 8, BB), 256, MMA_SMEM>>>();
    k_rz<<<MT/256, 256>>>();
    k_attn_t<<<dim3(16, 16, BB), 256>>>();
    k_wx<<<BB, 256>>>();
    k_av_mma<<<dim3(MT/128, CC/64), 256, MMA_SMEM>>>();
    k_conv_mma<<<dim3(MT/128, CC/64), 256, MMA_SMEM>>>(0, b1, x, out);
    k_conv_mma<<<dim3(MT/128, CC/64), 256, MMA_SMEM>>>(1, b2, x, out);
}